// round 1
// baseline (speedup 1.0000x reference)
#include <cuda_runtime.h>
#include <math.h>

// ---------------------------------------------------------------------------
// Scratch (device globals — no allocation allowed)
// ---------------------------------------------------------------------------
// Shapes: BT=8, spatial 32x32=1024, F=128 channels, heads=4, d=32
__device__ float g_bev_feat[8 * 128 * 1024];   // (bt, c, n)
__device__ float g_kv[8 * 192 * 1024];         // (bt, c, n): c<128 hd_feat, c>=128 front
__device__ float g_Q[8 * 4 * 1024 * 32];       // (bt, h, n, d)  (pre-scaled by 1/sqrt(d))
__device__ float g_K[8 * 4 * 1024 * 32];
__device__ float g_V[8 * 4 * 1024 * 32];
__device__ float g_attn[8 * 1024 * 128];       // (bt, n, c) c = h*32+d
__device__ float g_fused[8 * 128 * 1024];      // (bt, c, n)

// ---------------------------------------------------------------------------
// Conv 3x3, SAME padding, stride 1, with optional 16 broadcast "ego" channels
// appended after CIN regular channels. ReLU fused. Output stride configurable.
// grid: (16 oc-groups of 8, 8 bt), block: 256 threads.
// Double-buffered smem over input channels, single __syncthreads per channel.
// ---------------------------------------------------------------------------
template <int CIN, bool EGO>
__global__ __launch_bounds__(256) void conv3x3_relu_kernel(
    const float* __restrict__ in,    // (8, CIN, 32, 32)
    const float* __restrict__ ego,   // (8, 16) or nullptr
    const float* __restrict__ w,     // (128, CTOT, 3, 3)
    const float* __restrict__ bias,  // (128)
    float* __restrict__ out,         // (8, ld_out, 32, 32)
    int ld_out)
{
    constexpr int CTOT = CIN + (EGO ? 16 : 0);
    const int bt  = blockIdx.y;
    const int oc0 = blockIdx.x * 8;
    const int tid = threadIdx.x;
    const int row = tid >> 3;         // 0..31
    const int xq  = (tid & 7) * 4;    // 0,4,...,28

    // padded tile: 34 rows x 34 cols, row stride 35 (conflict-free)
    __shared__ float s_in[2][34 * 35];
    __shared__ float s_w[2][8 * 9];

    float acc[8][4];
#pragma unroll
    for (int j = 0; j < 8; j++) {
        float b = bias[oc0 + j];
#pragma unroll
        for (int p = 0; p < 4; p++) acc[j][p] = b;
    }

    // Precompute staging offsets for the 5 elements this thread stages.
    int soff[5];
    int gidx[5];
    bool inb[5];
#pragma unroll
    for (int k = 0; k < 5; k++) {
        int idx = tid + k * 256;
        bool valid = idx < 34 * 34;
        int y = valid ? (idx / 34 - 1) : 0;
        int x = valid ? (idx % 34 - 1) : 0;
        bool ib = valid && (unsigned)y < 32u && (unsigned)x < 32u;
        soff[k] = valid ? ((y + 1) * 35 + (x + 1)) : 0;
        gidx[k] = y * 32 + x;
        inb[k] = ib;
        if (!valid) soff[k] = -1;
    }
    const int wj = tid / 9, wt = tid - wj * 9;

    float pin[5];
    float pw = 0.f;

    // prefetch ic = 0
    {
        const float* src = in + (bt * CIN + 0) * 1024;
#pragma unroll
        for (int k = 0; k < 5; k++) pin[k] = inb[k] ? src[gidx[k]] : 0.f;
        if (tid < 72) pw = w[((oc0 + wj) * CTOT + 0) * 9 + wt];
    }

    for (int ic = 0; ic < CTOT; ic++) {
        const int b = ic & 1;
        // stage current
#pragma unroll
        for (int k = 0; k < 5; k++)
            if (soff[k] >= 0) s_in[b][soff[k]] = pin[k];
        if (tid < 72) s_w[b][wj * 9 + wt] = pw;

        // prefetch next
        if (ic + 1 < CTOT) {
            int icn = ic + 1;
            if (!EGO || icn < CIN) {
                const float* src = in + (bt * CIN + icn) * 1024;
#pragma unroll
                for (int k = 0; k < 5; k++) pin[k] = inb[k] ? src[gidx[k]] : 0.f;
            } else {
                float ev = ego[bt * 16 + (icn - CIN)];
#pragma unroll
                for (int k = 0; k < 5; k++) pin[k] = inb[k] ? ev : 0.f;
            }
            if (tid < 72) pw = w[((oc0 + wj) * CTOT + icn) * 9 + wt];
        }
        __syncthreads();

        // compute from buffer b
        const float* tile = s_in[b];
        const float* wrow = s_w[b];
#pragma unroll
        for (int ky = 0; ky < 3; ky++) {
            float r[6];
            const float* trow = tile + (row + ky) * 35 + xq;
#pragma unroll
            for (int k = 0; k < 6; k++) r[k] = trow[k];
#pragma unroll
            for (int kx = 0; kx < 3; kx++) {
#pragma unroll
                for (int j = 0; j < 8; j++) {
                    float wv = wrow[j * 9 + ky * 3 + kx];
#pragma unroll
                    for (int p = 0; p < 4; p++)
                        acc[j][p] = fmaf(r[p + kx], wv, acc[j][p]);
                }
            }
        }
        // NOTE: single barrier per iteration is safe with double buffering:
        // a thread staging buffer (b^1) at iter ic+1 has passed sync(ic),
        // which implies every thread finished compute(ic-1) on buffer (b^1).
    }

#pragma unroll
    for (int j = 0; j < 8; j++) {
        float4 v;
        v.x = fmaxf(acc[j][0], 0.f);
        v.y = fmaxf(acc[j][1], 0.f);
        v.z = fmaxf(acc[j][2], 0.f);
        v.w = fmaxf(acc[j][3], 0.f);
        *(float4*)(out + (size_t)(bt * ld_out + oc0 + j) * 1024 + row * 32 + xq) = v;
    }
}

// ---------------------------------------------------------------------------
// Bilinear resize 16x16 -> 32x32 (align_corners=False / half-pixel, edge clamp
// which matches jax.image.resize's renormalized triangle kernel for 2x upsample)
// Writes channels 128..191 of g_kv.
// ---------------------------------------------------------------------------
__global__ __launch_bounds__(256) void resize_front_kernel(
    const float* __restrict__ front)  // (8, 64, 16, 16)
{
    int idx = blockIdx.x * 256 + threadIdx.x;
    if (idx >= 8 * 64 * 1024) return;
    int px = idx & 1023;
    int c  = (idx >> 10) & 63;
    int bt = idx >> 16;
    int y = px >> 5, x = px & 31;

    float sy = y * 0.5f - 0.25f;
    float sx = x * 0.5f - 0.25f;
    int y0 = __float2int_rd(sy);
    int x0 = __float2int_rd(sx);
    float fy = sy - (float)y0;
    float fx = sx - (float)x0;
    int y0c = max(y0, 0), y1c = min(y0 + 1, 15);
    int x0c = max(x0, 0), x1c = min(x0 + 1, 15);

    const float* src = front + (bt * 64 + c) * 256;
    float a = src[y0c * 16 + x0c];
    float b = src[y0c * 16 + x1c];
    float cc = src[y1c * 16 + x0c];
    float d = src[y1c * 16 + x1c];
    float top = a + fx * (b - a);
    float bot = cc + fx * (d - cc);
    g_kv[(size_t)(bt * 192 + 128 + c) * 1024 + px] = top + fy * (bot - top);
}

// ---------------------------------------------------------------------------
// Projection: out[bt,h,n,d] = scale * sum_c X[bt,c,n] * W[h*32+d, c]
// grid: (16 n-tiles of 64, 8 bt), block 256. Tile 64n x 128o, K-chunks of 16.
// ---------------------------------------------------------------------------
__global__ __launch_bounds__(256) void proj_qkv_kernel(
    const float* __restrict__ X,   // (8, C, 1024)
    const float* __restrict__ W,   // (128, C)
    float* __restrict__ out,       // (8, 4, 1024, 32)
    int C, float scale)
{
    const int bt = blockIdx.y;
    const int n0 = blockIdx.x * 64;
    const int tid = threadIdx.x;
    const int tn = tid & 15;
    const int to = tid >> 4;

    __shared__ float sX[16][68];
    __shared__ float sW[16][132];

    float acc[4][8];
#pragma unroll
    for (int i = 0; i < 4; i++)
#pragma unroll
        for (int j = 0; j < 8; j++) acc[i][j] = 0.f;

    const int lc = tid >> 4;
    const int ln = (tid & 15) * 4;
    const int lo = tid & 127;
    const int lwc = (tid >> 7) * 8;

    for (int c0 = 0; c0 < C; c0 += 16) {
        float4 xv = *(const float4*)&X[(size_t)(bt * C + c0 + lc) * 1024 + n0 + ln];
        sX[lc][ln + 0] = xv.x; sX[lc][ln + 1] = xv.y;
        sX[lc][ln + 2] = xv.z; sX[lc][ln + 3] = xv.w;
#pragma unroll
        for (int k = 0; k < 8; k++) sW[lwc + k][lo] = W[lo * C + c0 + lwc + k];
        __syncthreads();
#pragma unroll
        for (int c = 0; c < 16; c++) {
            float xr[4], wr[8];
#pragma unroll
            for (int i = 0; i < 4; i++) xr[i] = sX[c][tn * 4 + i];
#pragma unroll
            for (int j = 0; j < 8; j++) wr[j] = sW[c][to * 8 + j];
#pragma unroll
            for (int i = 0; i < 4; i++)
#pragma unroll
                for (int j = 0; j < 8; j++)
                    acc[i][j] = fmaf(xr[i], wr[j], acc[i][j]);
        }
        __syncthreads();
    }

#pragma unroll
    for (int i = 0; i < 4; i++) {
        int n = n0 + tn * 4 + i;
#pragma unroll
        for (int j = 0; j < 8; j++) {
            int o = to * 8 + j;
            out[(size_t)bt * 131072 + (o >> 5) * 32768 + n * 32 + (o & 31)] =
                acc[i][j] * scale;
        }
    }
}

// ---------------------------------------------------------------------------
// Attention: one thread = one query (online softmax), K/V tiles staged in smem.
// grid: (8 q-tiles of 128, 4 heads, 8 bt), block 128.
// Q was pre-scaled by 1/sqrt(32) in its projection.
// ---------------------------------------------------------------------------
__global__ __launch_bounds__(128) void attention_kernel()
{
    const int q0 = blockIdx.x * 128;
    const int h  = blockIdx.y;
    const int bt = blockIdx.z;
    const int tid = threadIdx.x;
    const int n = q0 + tid;
    const size_t base = (size_t)(bt * 4 + h) * 1024 * 32;

    float q[32];
    {
        const float4* qp = (const float4*)(g_Q + base + (size_t)n * 32);
#pragma unroll
        for (int i = 0; i < 8; i++) {
            float4 v = qp[i];
            q[4 * i] = v.x; q[4 * i + 1] = v.y; q[4 * i + 2] = v.z; q[4 * i + 3] = v.w;
        }
    }
    float m = -1e30f, l = 0.f;
    float acc[32];
#pragma unroll
    for (int i = 0; i < 32; i++) acc[i] = 0.f;

    __shared__ float4 sK[128 * 8];
    __shared__ float4 sV[128 * 8];

    for (int kt = 0; kt < 8; kt++) {
        const float4* kp = (const float4*)(g_K + base + (size_t)kt * 128 * 32);
        const float4* vp = (const float4*)(g_V + base + (size_t)kt * 128 * 32);
#pragma unroll
        for (int r = 0; r < 8; r++) {
            sK[tid + r * 128] = kp[tid + r * 128];
            sV[tid + r * 128] = vp[tid + r * 128];
        }
        __syncthreads();

        for (int j = 0; j < 128; j++) {
            const float4* krow = sK + j * 8;
            float s0 = 0.f, s1 = 0.f, s2 = 0.f, s3 = 0.f;
#pragma unroll
            for (int i = 0; i < 8; i++) {
                float4 kv4 = krow[i];
                s0 = fmaf(q[4 * i],     kv4.x, s0);
                s1 = fmaf(q[4 * i + 1], kv4.y, s1);
                s2 = fmaf(q[4 * i + 2], kv4.z, s2);
                s3 = fmaf(q[4 * i + 3], kv4.w, s3);
            }
            float s = (s0 + s1) + (s2 + s3);
            const float4* vrow = sV + j * 8;
            if (s > m) {
                float corr = __expf(m - s);
                l = l * corr + 1.f;
                m = s;
#pragma unroll
                for (int i = 0; i < 8; i++) {
                    float4 vv = vrow[i];
                    acc[4 * i]     = fmaf(acc[4 * i],     corr, vv.x);
                    acc[4 * i + 1] = fmaf(acc[4 * i + 1], corr, vv.y);
                    acc[4 * i + 2] = fmaf(acc[4 * i + 2], corr, vv.z);
                    acc[4 * i + 3] = fmaf(acc[4 * i + 3], corr, vv.w);
                }
            } else {
                float p = __expf(s - m);
                l += p;
#pragma unroll
                for (int i = 0; i < 8; i++) {
                    float4 vv = vrow[i];
                    acc[4 * i]     = fmaf(p, vv.x, acc[4 * i]);
                    acc[4 * i + 1] = fmaf(p, vv.y, acc[4 * i + 1]);
                    acc[4 * i + 2] = fmaf(p, vv.z, acc[4 * i + 2]);
                    acc[4 * i + 3] = fmaf(p, vv.w, acc[4 * i + 3]);
                }
            }
        }
        __syncthreads();
    }

    float inv = 1.f / l;
    float4* op = (float4*)(g_attn + (size_t)(bt * 1024 + n) * 128 + h * 32);
#pragma unroll
    for (int i = 0; i < 8; i++) {
        float4 v;
        v.x = acc[4 * i] * inv;
        v.y = acc[4 * i + 1] * inv;
        v.z = acc[4 * i + 2] * inv;
        v.w = acc[4 * i + 3] * inv;
        op[i] = v;
    }
}

// ---------------------------------------------------------------------------
// Output projection: g_fused[bt,o,n] = sum_c g_attn[bt,n,c] * wo[o,c] + bo[o]
// ---------------------------------------------------------------------------
__global__ __launch_bounds__(256) void proj_out_kernel(
    const float* __restrict__ W,    // (128, 128) wo
    const float* __restrict__ bias) // (128) bo
{
    const int bt = blockIdx.y;
    const int n0 = blockIdx.x * 64;
    const int tid = threadIdx.x;
    const int tn = tid & 15;
    const int to = tid >> 4;

    __shared__ float sX[16][68];
    __shared__ float sW[16][132];

    float acc[4][8];
#pragma unroll
    for (int j = 0; j < 8; j++) {
        float b = bias[to * 8 + j];
#pragma unroll
        for (int i = 0; i < 4; i++) acc[i][j] = b;
    }

    const int ln = tid & 63;
    const int lcc = (tid >> 6) * 4;
    const int lo = tid & 127;
    const int lwc = (tid >> 7) * 8;

    for (int c0 = 0; c0 < 128; c0 += 16) {
        float4 av = *(const float4*)&g_attn[(size_t)(bt * 1024 + n0 + ln) * 128 + c0 + lcc];
        sX[lcc + 0][ln] = av.x; sX[lcc + 1][ln] = av.y;
        sX[lcc + 2][ln] = av.z; sX[lcc + 3][ln] = av.w;
#pragma unroll
        for (int k = 0; k < 8; k++) sW[lwc + k][lo] = W[lo * 128 + c0 + lwc + k];
        __syncthreads();
#pragma unroll
        for (int c = 0; c < 16; c++) {
            float xr[4], wr[8];
#pragma unroll
            for (int i = 0; i < 4; i++) xr[i] = sX[c][tn * 4 + i];
#pragma unroll
            for (int j = 0; j < 8; j++) wr[j] = sW[c][to * 8 + j];
#pragma unroll
            for (int i = 0; i < 4; i++)
#pragma unroll
                for (int j = 0; j < 8; j++)
                    acc[i][j] = fmaf(xr[i], wr[j], acc[i][j]);
        }
        __syncthreads();
    }

#pragma unroll
    for (int j = 0; j < 8; j++) {
        int o = to * 8 + j;
#pragma unroll
        for (int i = 0; i < 4; i++) {
            int n = n0 + tn * 4 + i;
            g_fused[(size_t)(bt * 128 + o) * 1024 + n] = acc[i][j];
        }
    }
}

// ---------------------------------------------------------------------------
// Launch
// ---------------------------------------------------------------------------
extern "C" void kernel_launch(void* const* d_in, const int* in_sizes, int n_in,
                              void* d_out, int out_size)
{
    const float* bev   = (const float*)d_in[0];
    const float* hd    = (const float*)d_in[1];
    const float* ego   = (const float*)d_in[2];
    const float* front = (const float*)d_in[3];
    const float* w_bev = (const float*)d_in[4];
    const float* b_bev = (const float*)d_in[5];
    const float* w_hd  = (const float*)d_in[6];
    const float* b_hd  = (const float*)d_in[7];
    const float* wq    = (const float*)d_in[8];
    const float* wk    = (const float*)d_in[9];
    const float* wv    = (const float*)d_in[10];
    const float* wo    = (const float*)d_in[11];
    const float* bo    = (const float*)d_in[12];
    const float* w_out = (const float*)d_in[13];
    const float* b_out = (const float*)d_in[14];
    float* out = (float*)d_out;

    float *p_bev_feat, *p_kv, *p_fused, *p_Q, *p_K, *p_V;
    cudaGetSymbolAddress((void**)&p_bev_feat, g_bev_feat);
    cudaGetSymbolAddress((void**)&p_kv, g_kv);
    cudaGetSymbolAddress((void**)&p_fused, g_fused);
    cudaGetSymbolAddress((void**)&p_Q, g_Q);
    cudaGetSymbolAddress((void**)&p_K, g_K);
    cudaGetSymbolAddress((void**)&p_V, g_V);

    const float scale = 0.17677669529663687f;  // 32^-0.5

    // Stage 1: input convs + front resize
    conv3x3_relu_kernel<128, true><<<dim3(16, 8), 256>>>(
        bev, ego, w_bev, b_bev, p_bev_feat, 128);
    conv3x3_relu_kernel<64, false><<<dim3(16, 8), 256>>>(
        hd, nullptr, w_hd, b_hd, p_kv, 192);
    resize_front_kernel<<<2048, 256>>>(front);

    // Stage 2: projections (Q pre-scaled)
    proj_qkv_kernel<<<dim3(16, 8), 256>>>(p_bev_feat, wq, p_Q, 128, scale);
    proj_qkv_kernel<<<dim3(16, 8), 256>>>(p_kv, wk, p_K, 192, 1.0f);
    proj_qkv_kernel<<<dim3(16, 8), 256>>>(p_kv, wv, p_V, 192, 1.0f);

    // Stage 3: attention
    attention_kernel<<<dim3(8, 4, 8), 128>>>();

    // Stage 4: output projection
    proj_out_kernel<<<dim3(16, 8), 256>>>(wo, bo);

    // Stage 5: final conv (reads g_fused + ego, writes d_out)
    conv3x3_relu_kernel<128, true><<<dim3(16, 8), 256>>>(
        p_fused, ego, w_out, b_out, out, 128);
}